// round 16
// baseline (speedup 1.0000x reference)
#include <cuda_runtime.h>
#include <cuda_bf16.h>
#include <cstdint>

#define BATCH 256
#define EMBED 512
#define NCLS 100000
#define NSUB 3
#define NSROWS (NCLS*NSUB)

#define NT 96       // subcenter rows per CTA (= 32 classes)
#define KC 64       // K chunk
#define CHUNKS 8
#define RING 4
#define THREADS 512
#define NCTAS (NCLS/32)     // 3125

#define COSM 0.8775825618903728f
#define SINM 0.479425538604203f
#define THv (-0.8775825618903728f)
#define MMc 0.2397127693021015f
#define SCALE 64.0f

#define A_ST   32768                 // 256 rows x 128B bf16, SW128
#define BB_ST  12288                 // 96 rows x 128B bf16, SW128
#define AOFF   0
#define BBOFF  (RING*A_ST)            // 131072
#define WSQ_OFF (BBOFF + RING*BB_ST)  // 180224
#define MBAR_OFF (WSQ_OFF + 96*4)     // 180608  (full[4], free[4])
#define SMEM_BYTES (MBAR_OFF + 128)   // 180736
#define EPI_STRIDE 97

#define SW(o) ((o) ^ (((o) >> 3) & 0x70))

__device__ __nv_bfloat16 g_ebf[BATCH*EMBED];
__device__ float g_sumexp[BATCH];
__device__ float g_lablogit[BATCH];
__device__ float g_expadj[BATCH];
__device__ unsigned int g_ticket;

__device__ __forceinline__ float fexp(float x){
    float y = x * 1.4426950408889634f;
    int   n = __float2int_rn(y);
    float f = y - (float)n;
    float p = fmaf(f, 1.3333558e-3f, 9.6181291e-3f);
    p = fmaf(f, p, 5.5504109e-2f);
    p = fmaf(f, p, 2.4022651e-1f);
    p = fmaf(f, p, 6.9314718e-1f);
    p = fmaf(f, p, 1.0f);
    return p * __int_as_float((n + 127) << 23);
}

__device__ __forceinline__ uint32_t smem_u32(const void* p){
    return (uint32_t)__cvta_generic_to_shared(p);
}
__device__ __forceinline__ void mbar_init(uint32_t a, uint32_t cnt){
    asm volatile("mbarrier.init.shared.b64 [%0], %1;" :: "r"(a), "r"(cnt) : "memory");
}
__device__ __forceinline__ void mbar_arrive(uint32_t a){
    asm volatile("mbarrier.arrive.shared.b64 _, [%0];" :: "r"(a) : "memory");
}
__device__ __forceinline__ void mbar_wait(uint32_t a, uint32_t parity){
    asm volatile(
        "{\n\t.reg .pred P1;\n\t"
        "WL%=:\n\t"
        "mbarrier.try_wait.parity.acquire.cta.shared::cta.b64 P1, [%0], %1, 0x989680;\n\t"
        "@P1 bra.uni WD%=;\n\t"
        "bra.uni WL%=;\n\t"
        "WD%=:\n\t}"
        :: "r"(a), "r"(parity) : "memory");
}

// kernel 1 (fused): blocks 0..255 normalize embeddings -> bf16 scratch;
// blocks 256..319: exact fp32 label logits + sumexp correction (1 warp/row)
__global__ void prep_label(const float* __restrict__ emb,
                           const float* __restrict__ W,
                           const void*  __restrict__ labels_raw){
    if (blockIdx.x < 256){
        int row = blockIdx.x;
        int t = threadIdx.x;    // 128
        float4 v = reinterpret_cast<const float4*>(emb + (size_t)row*EMBED)[t];
        float ss = v.x*v.x + v.y*v.y + v.z*v.z + v.w*v.w;
        #pragma unroll
        for (int o=16;o;o>>=1) ss += __shfl_xor_sync(0xffffffffu, ss, o);
        __shared__ float wss[4];
        if ((t & 31) == 0) wss[t>>5] = ss;
        __syncthreads();
        float tot = wss[0]+wss[1]+wss[2]+wss[3];
        float inv = 1.0f / fmaxf(sqrtf(tot), 1e-12f);
        __nv_bfloat162 p0 = __float22bfloat162_rn(make_float2(v.x*inv, v.y*inv));
        __nv_bfloat162 p1 = __float22bfloat162_rn(make_float2(v.z*inv, v.w*inv));
        uint2 u;
        u.x = *reinterpret_cast<uint32_t*>(&p0);
        u.y = *reinterpret_cast<uint32_t*>(&p1);
        reinterpret_cast<uint2*>(g_ebf + (size_t)row*EMBED)[t] = u;
        if (t == 0) g_sumexp[row] = 0.0f;
        return;
    }
    int row  = (blockIdx.x - 256)*4 + (threadIdx.x >> 5);
    int lane = threadIdx.x & 31;

    const long long* l64 = (const long long*)labels_raw;
    const int*       l32 = (const int*)labels_raw;
    bool is64 = true;
    #pragma unroll
    for (int i=0;i<8;i++){
        long long v = l64[i];
        if (v < 0 || v >= (long long)NCLS) is64 = false;
    }
    long long lab = is64 ? l64[row] : (long long)l32[row];

    const float* e  = emb + (size_t)row*EMBED;
    const float* w0 = W   + (size_t)lab*NSUB*EMBED;

    float ess = 0.0f;
    float dot0=0.f, dot1=0.f, dot2=0.f;
    float ws0=0.f, ws1=0.f, ws2=0.f;
    for (int k = lane; k < EMBED; k += 32){
        float ev = e[k];
        ess = fmaf(ev, ev, ess);
        float a = w0[k];
        float b = w0[EMBED + k];
        float c = w0[2*EMBED + k];
        dot0 = fmaf(ev, a, dot0); ws0 = fmaf(a, a, ws0);
        dot1 = fmaf(ev, b, dot1); ws1 = fmaf(b, b, ws1);
        dot2 = fmaf(ev, c, dot2); ws2 = fmaf(c, c, ws2);
    }
    #pragma unroll
    for (int o=16;o;o>>=1){
        ess  += __shfl_xor_sync(0xffffffffu, ess,  o);
        dot0 += __shfl_xor_sync(0xffffffffu, dot0, o);
        dot1 += __shfl_xor_sync(0xffffffffu, dot1, o);
        dot2 += __shfl_xor_sync(0xffffffffu, dot2, o);
        ws0  += __shfl_xor_sync(0xffffffffu, ws0,  o);
        ws1  += __shfl_xor_sync(0xffffffffu, ws1,  o);
        ws2  += __shfl_xor_sync(0xffffffffu, ws2,  o);
    }
    if (lane == 0){
        float einv = 1.0f / fmaxf(sqrtf(ess), 1e-12f);
        float c0 = dot0 * einv / fmaxf(sqrtf(ws0), 1e-12f);
        float c1 = dot1 * einv / fmaxf(sqrtf(ws1), 1e-12f);
        float c2 = dot2 * einv / fmaxf(sqrtf(ws2), 1e-12f);
        float cs = fmaxf(c0, fmaxf(c1, c2));
        float sine = sqrtf(fmaxf(1.0f - cs*cs, 0.0f));
        float phi = (cs > THv) ? (cs*COSM - sine*SINM) : (cs - MMc);
        float ll = SCALE * phi;
        g_lablogit[row] = ll;
        g_expadj[row] = fexp(ll) - fexp(SCALE * cs);
    }
}

// kernel 2: warp-specialized pipelined bf16 GEMM (no CTA barrier in mainloop)
// warps 0..11 consumers (4M x 3N, tile 64x32); warps 12..15 producers
__global__ void __launch_bounds__(THREADS, 1)
arc_main(const float* __restrict__ W, float* __restrict__ out){
    extern __shared__ char smem[];
    float* s_wsq = reinterpret_cast<float*>(smem + WSQ_OFF);
    float* epi   = reinterpret_cast<float*>(smem);   // reuse pipeline smem after loop

    const int tid  = threadIdx.x;
    const int lane = tid & 31, warp = tid >> 5;
    const uint32_t smem_base = smem_u32(smem);
    const uint32_t mb_full = smem_base + MBAR_OFF;
    const uint32_t mb_free = smem_base + MBAR_OFF + RING*8;
    const int n0 = blockIdx.x * NT;

    if (tid == 0){
        #pragma unroll
        for (int s=0;s<RING;s++){
            mbar_init(mb_full + s*8, 128);   // producers: 128 threads
            mbar_init(mb_free + s*8, 384);   // consumers: 384 threads
        }
    }
    __syncthreads();

    float acc[4][4][4];
    float bsq[12];
    #pragma unroll
    for (int i=0;i<12;i++) bsq[i] = 0.0f;

    if (warp < 12){
        // ───────── consumers ─────────
        const int wm = warp & 3, wn = warp >> 2;   // 4 M x 3 N, warp tile 64x32
        #pragma unroll
        for (int a=0;a<4;a++)
          #pragma unroll
          for (int b=0;b<4;b++)
            #pragma unroll
            for (int c=0;c<4;c++) acc[a][b][c] = 0.0f;

        #pragma unroll 1
        for (int kc=0; kc<CHUNKS; kc++){
            int s = kc & (RING-1);
            mbar_wait(mb_full + s*8, (uint32_t)((kc >> 2) & 1));
            const char* Ab = smem + AOFF + s*A_ST;
            const char* Bb = smem + BBOFF + s*BB_ST;
            #pragma unroll
            for (int kk=0; kk<4; kk++){
                uint32_t af[4][4];
                #pragma unroll
                for (int mt=0; mt<4; mt++){
                    int r = wm*64 + mt*16 + (lane & 15);
                    uint32_t o = (uint32_t)(r*128 + kk*32 + (lane >> 4)*16);
                    uint32_t addr = smem_u32(Ab) + SW(o);
                    asm volatile("ldmatrix.sync.aligned.m8n8.x4.shared.b16 {%0,%1,%2,%3}, [%4];\n"
                                 : "=r"(af[mt][0]), "=r"(af[mt][1]), "=r"(af[mt][2]), "=r"(af[mt][3])
                                 : "r"(addr));
                }
                uint32_t bfr[4][2];
                #pragma unroll
                for (int pr=0; pr<2; pr++){
                    int grp = lane >> 3;
                    int row = wn*32 + pr*16 + ((grp >> 1) << 3) + (lane & 7);
                    uint32_t o = (uint32_t)(row*128 + kk*32 + (grp & 1)*16);
                    uint32_t addr = smem_u32(Bb) + SW(o);
                    asm volatile("ldmatrix.sync.aligned.m8n8.x4.shared.b16 {%0,%1,%2,%3}, [%4];\n"
                                 : "=r"(bfr[2*pr][0]), "=r"(bfr[2*pr][1]),
                                   "=r"(bfr[2*pr+1][0]), "=r"(bfr[2*pr+1][1])
                                 : "r"(addr));
                }
                #pragma unroll
                for (int mt=0; mt<4; mt++)
                    #pragma unroll
                    for (int nt=0; nt<4; nt++){
                        float* d = acc[mt][nt];
                        asm volatile(
                          "mma.sync.aligned.m16n8k16.row.col.f32.bf16.bf16.f32 "
                          "{%0,%1,%2,%3}, {%4,%5,%6,%7}, {%8,%9}, {%0,%1,%2,%3};\n"
                          : "+f"(d[0]), "+f"(d[1]), "+f"(d[2]), "+f"(d[3])
                          : "r"(af[mt][0]), "r"(af[mt][1]), "r"(af[mt][2]), "r"(af[mt][3]),
                            "r"(bfr[nt][0]), "r"(bfr[nt][1]));
                    }
            }
            mbar_arrive(mb_free + s*8);
        }
    } else {
        // ───────── producers ─────────
        const int ptid = tid - 384;        // 0..127
        const float* Wbase = W + (size_t)n0*EMBED;
        #pragma unroll 1
        for (int kc=0; kc<CHUNKS; kc++){
            int s = kc & (RING-1);
            mbar_wait(mb_free + s*8, (uint32_t)(((kc >> 2) + 1) & 1));
            // A: 256 rows x 128B -> SW128 swizzled slot
            uint32_t a_dst = smem_base + AOFF + s*A_ST;
            const __nv_bfloat16* a_src = g_ebf + kc*KC;
            #pragma unroll
            for (int p=0;p<16;p++){
                int idx = p*128 + ptid;
                int r = idx >> 3, q = idx & 7;
                uint32_t o = (uint32_t)(r*128 + q*16);
                const void* sp = a_src + (size_t)r*EMBED + q*8;
                asm volatile("cp.async.cg.shared.global [%0], [%1], 16;\n"
                             :: "r"(a_dst + SW(o)), "l"(sp));
            }
            asm volatile("cp.async.commit_group;\n");
            // B: 96 rows x 64 fp32 via LDG, cvt, swizzled STS
            float4 vB[12];
            const float* bsrc = Wbase + kc*KC;
            #pragma unroll
            for (int i=0;i<12;i++){
                int idx = i*128 + ptid;
                int r = idx >> 4, q = idx & 15;
                vB[i] = *reinterpret_cast<const float4*>(bsrc + (size_t)r*EMBED + q*4);
            }
            char* Bb = smem + BBOFF + s*BB_ST;
            #pragma unroll
            for (int i=0;i<12;i++){
                int idx = i*128 + ptid;
                int r = idx >> 4, q = idx & 15;
                float4 v = vB[i];
                bsq[i] += fmaf(v.x,v.x, fmaf(v.y,v.y, fmaf(v.z,v.z, v.w*v.w)));
                uint32_t lo, hi;
                asm volatile("cvt.rn.bf16x2.f32 %0, %1, %2;\n" : "=r"(lo) : "f"(v.y), "f"(v.x));
                asm volatile("cvt.rn.bf16x2.f32 %0, %1, %2;\n" : "=r"(hi) : "f"(v.w), "f"(v.z));
                uint32_t o = (uint32_t)(r*128 + q*8);
                *reinterpret_cast<uint2*>(Bb + SW(o)) = make_uint2(lo, hi);
            }
            asm volatile("cp.async.wait_group 0;\n");
            mbar_arrive(mb_full + s*8);     // release: A + bb of stage s ready
        }
    }

    __syncthreads();      // mainloop done everywhere

    // producers publish ||w||^2 (each (i, ptid>>4) row reduced over 16 lanes)
    if (warp >= 12){
        int ptid = tid - 384;
        #pragma unroll
        for (int i=0;i<12;i++){
            float v = bsq[i];
            v += __shfl_xor_sync(0xffffffffu, v, 1, 16);
            v += __shfl_xor_sync(0xffffffffu, v, 2, 16);
            v += __shfl_xor_sync(0xffffffffu, v, 4, 16);
            v += __shfl_xor_sync(0xffffffffu, v, 8, 16);
            if ((ptid & 15) == 0) s_wsq[i*8 + (ptid >> 4)] = v;
        }
    }
    __syncthreads();
    if (tid < NT) s_wsq[tid] = rsqrtf(fmaxf(s_wsq[tid], 1e-24f));
    __syncthreads();

    // consumers stage scaled cosines into epi (256 x 96, stride 97)
    if (warp < 12){
        const int wm = warp & 3, wn = warp >> 2;
        const int g = lane >> 2, tg = lane & 3;
        #pragma unroll
        for (int mt=0; mt<4; mt++)
            #pragma unroll
            for (int nt=0; nt<4; nt++){
                int c0 = wn*32 + nt*8 + 2*tg;
                float i0 = s_wsq[c0], i1 = s_wsq[c0+1];
                int r0 = wm*64 + mt*16 + g;
                epi[ r0     *EPI_STRIDE + c0    ] = acc[mt][nt][0]*i0;
                epi[ r0     *EPI_STRIDE + c0 + 1] = acc[mt][nt][1]*i1;
                epi[(r0 + 8)*EPI_STRIDE + c0    ] = acc[mt][nt][2]*i0;
                epi[(r0 + 8)*EPI_STRIDE + c0 + 1] = acc[mt][nt][3]*i1;
            }
    }
    __syncthreads();

    // all 512 threads: one row-half (16 classes) each -> max3 + sumexp
    {
        int row = tid >> 1;
        int cb  = (tid & 1) * 48;
        const float* rp = epi + (size_t)row*EPI_STRIDE + cb;
        float partial = 0.0f;
        #pragma unroll
        for (int c=0; c<16; c++){
            float v0 = rp[c*3], v1 = rp[c*3+1], v2 = rp[c*3+2];
            float cs = fmaxf(v0, fmaxf(v1, v2));
            partial += fexp(SCALE * cs);
        }
        atomicAdd(&g_sumexp[row], partial);
    }

    // ── inline finalize by the last CTA (atomic ticket) ──
    __threadfence();
    __syncthreads();
    __shared__ unsigned int s_flag;
    if (tid == 0){
        unsigned int old = atomicAdd(&g_ticket, 1u);
        s_flag = (old == (unsigned)(NCTAS - 1)) ? 1u : 0u;
    }
    __syncthreads();
    if (s_flag){
        __threadfence();
        float v = 0.0f;
        if (tid < BATCH){
            float S = __ldcg(&g_sumexp[tid]) + g_expadj[tid];
            v = logf(S) - g_lablogit[tid];
        }
        #pragma unroll
        for (int o=16;o;o>>=1) v += __shfl_xor_sync(0xffffffffu, v, o);
        float* ws = epi;
        if ((tid & 31) == 0) ws[tid>>5] = v;
        __syncthreads();
        if (tid == 0){
            float s = 0.0f;
            #pragma unroll
            for (int i=0;i<8;i++) s += ws[i];
            out[0] = s * (1.0f/256.0f);
            g_ticket = 0;
        }
    }
}

extern "C" void kernel_launch(void* const* d_in, const int* in_sizes, int n_in,
                              void* d_out, int out_size){
    int ie = 0, il = 1, iw = 2;
    for (int i = 0; i < n_in; i++){
        if (in_sizes[i] == BATCH) il = i;
        else if (in_sizes[i] == BATCH*EMBED) ie = i;
        else if (in_sizes[i] == NSROWS*EMBED) iw = i;
    }
    const float* emb    = (const float*)d_in[ie];
    const void*  labels = (const void*)d_in[il];
    const float* W      = (const float*)d_in[iw];

    cudaFuncSetAttribute(arc_main, cudaFuncAttributeMaxDynamicSharedMemorySize, SMEM_BYTES);

    prep_label<<<320, 128>>>(emb, W, labels);
    arc_main<<<NCTAS, THREADS, SMEM_BYTES>>>(W, (float*)d_out);
}

// round 17
// speedup vs baseline: 1.0737x; 1.0737x over previous
#include <cuda_runtime.h>
#include <cuda_bf16.h>
#include <cstdint>

#define BATCH 256
#define EMBED 512
#define NCLS 100000
#define NSUB 3
#define NSROWS (NCLS*NSUB)

#define MT 128      // M rows per CTA (batch split in 2)
#define NT 96       // subcenter rows per CTA (= 32 classes)
#define KC 64       // K chunk
#define CHUNKS 8
#define THREADS 256
#define TOTAL_CTAS (2*(NCLS/32))    // 6250
#define EPI_STRIDE 49

#define COSM 0.8775825618903728f
#define SINM 0.479425538604203f
#define THv (-0.8775825618903728f)
#define MMc 0.2397127693021015f
#define SCALE 64.0f

// swizzled, unpadded tiles
#define A_ST   16384                 // 128 rows x 128B bf16, SW128
#define BB_ST  12288                 // 96 rows x 128B bf16, SW128
#define AOFF   0
#define BBOFF  (4*A_ST)              // 65536   (A ring = 4)
#define WSQ_OFF (BBOFF + 2*BB_ST)    // 90112   (bb ring = 2)
#define SMEM_BYTES (WSQ_OFF + 384)   // 90496

#define SW(o) ((o) ^ (((o) >> 3) & 0x70))

__device__ __nv_bfloat16 g_ebf[BATCH*EMBED];
__device__ float g_sumexp[BATCH];
__device__ float g_lablogit[BATCH];
__device__ float g_expadj[BATCH];
__device__ unsigned int g_ticket;

// fast exp via FMA-pipe polynomial (avoid MUFU.EX2 throughput wall)
__device__ __forceinline__ float fexp(float x){
    float y = x * 1.4426950408889634f;
    int   n = __float2int_rn(y);
    float f = y - (float)n;
    float p = fmaf(f, 1.3333558e-3f, 9.6181291e-3f);
    p = fmaf(f, p, 5.5504109e-2f);
    p = fmaf(f, p, 2.4022651e-1f);
    p = fmaf(f, p, 6.9314718e-1f);
    p = fmaf(f, p, 1.0f);
    return p * __int_as_float((n + 127) << 23);
}

__device__ __forceinline__ uint32_t smem_u32(const void* p){
    return (uint32_t)__cvta_generic_to_shared(p);
}

// kernel 1 (fused): blocks 0..255 normalize embeddings -> bf16 scratch;
// blocks 256..319: exact fp32 label logits + sumexp correction (1 warp/row)
__global__ void prep_label(const float* __restrict__ emb,
                           const float* __restrict__ W,
                           const void*  __restrict__ labels_raw){
    if (blockIdx.x < 256){
        int row = blockIdx.x;
        int t = threadIdx.x;    // 128
        float4 v = reinterpret_cast<const float4*>(emb + (size_t)row*EMBED)[t];
        float ss = v.x*v.x + v.y*v.y + v.z*v.z + v.w*v.w;
        #pragma unroll
        for (int o=16;o;o>>=1) ss += __shfl_xor_sync(0xffffffffu, ss, o);
        __shared__ float wss[4];
        if ((t & 31) == 0) wss[t>>5] = ss;
        __syncthreads();
        float tot = wss[0]+wss[1]+wss[2]+wss[3];
        float inv = 1.0f / fmaxf(sqrtf(tot), 1e-12f);
        __nv_bfloat162 p0 = __float22bfloat162_rn(make_float2(v.x*inv, v.y*inv));
        __nv_bfloat162 p1 = __float22bfloat162_rn(make_float2(v.z*inv, v.w*inv));
        uint2 u;
        u.x = *reinterpret_cast<uint32_t*>(&p0);
        u.y = *reinterpret_cast<uint32_t*>(&p1);
        reinterpret_cast<uint2*>(g_ebf + (size_t)row*EMBED)[t] = u;
        if (t == 0) g_sumexp[row] = 0.0f;
        return;
    }
    int row  = (blockIdx.x - 256)*4 + (threadIdx.x >> 5);
    int lane = threadIdx.x & 31;

    const long long* l64 = (const long long*)labels_raw;
    const int*       l32 = (const int*)labels_raw;
    bool is64 = true;
    #pragma unroll
    for (int i=0;i<8;i++){
        long long v = l64[i];
        if (v < 0 || v >= (long long)NCLS) is64 = false;
    }
    long long lab = is64 ? l64[row] : (long long)l32[row];

    const float* e  = emb + (size_t)row*EMBED;
    const float* w0 = W   + (size_t)lab*NSUB*EMBED;

    float ess = 0.0f;
    float dot0=0.f, dot1=0.f, dot2=0.f;
    float ws0=0.f, ws1=0.f, ws2=0.f;
    for (int k = lane; k < EMBED; k += 32){
        float ev = e[k];
        ess = fmaf(ev, ev, ess);
        float a = w0[k];
        float b = w0[EMBED + k];
        float c = w0[2*EMBED + k];
        dot0 = fmaf(ev, a, dot0); ws0 = fmaf(a, a, ws0);
        dot1 = fmaf(ev, b, dot1); ws1 = fmaf(b, b, ws1);
        dot2 = fmaf(ev, c, dot2); ws2 = fmaf(c, c, ws2);
    }
    #pragma unroll
    for (int o=16;o;o>>=1){
        ess  += __shfl_xor_sync(0xffffffffu, ess,  o);
        dot0 += __shfl_xor_sync(0xffffffffu, dot0, o);
        dot1 += __shfl_xor_sync(0xffffffffu, dot1, o);
        dot2 += __shfl_xor_sync(0xffffffffu, dot2, o);
        ws0  += __shfl_xor_sync(0xffffffffu, ws0,  o);
        ws1  += __shfl_xor_sync(0xffffffffu, ws1,  o);
        ws2  += __shfl_xor_sync(0xffffffffu, ws2,  o);
    }
    if (lane == 0){
        float einv = 1.0f / fmaxf(sqrtf(ess), 1e-12f);
        float c0 = dot0 * einv / fmaxf(sqrtf(ws0), 1e-12f);
        float c1 = dot1 * einv / fmaxf(sqrtf(ws1), 1e-12f);
        float c2 = dot2 * einv / fmaxf(sqrtf(ws2), 1e-12f);
        float cs = fmaxf(c0, fmaxf(c1, c2));
        float sine = sqrtf(fmaxf(1.0f - cs*cs, 0.0f));
        float phi = (cs > THv) ? (cs*COSM - sine*SINM) : (cs - MMc);
        float ll = SCALE * phi;
        g_lablogit[row] = ll;
        g_expadj[row] = fexp(ll) - fexp(SCALE * cs);
    }
}

// kernel 2: 2 CTAs/SM (M split), single-barrier-per-chunk pipelined bf16 GEMM
// grid (2, 3125): x = M half (launch-adjacent pairs share W rows via L2)
// epoch kc: [issueA(kc+2) | ldgB(kc+1) | wait | SYNC | mma(kc) | cvt+STS bb(kc+1)]
__global__ void __launch_bounds__(THREADS, 2)
arc_main(const float* __restrict__ W, float* __restrict__ out){
    extern __shared__ char smem[];
    float* s_wsq = reinterpret_cast<float*>(smem + WSQ_OFF);
    float* epi   = reinterpret_cast<float*>(smem);   // reuse pipeline smem after loop

    const int tid  = threadIdx.x;
    const int lane = tid & 31, warp = tid >> 5;
    const int g = lane >> 2, tg = lane & 3;
    const int wm = warp & 3, wn = warp >> 2;     // 4 M-warps x 2 N-warps, tile 32x48

    const int m0 = blockIdx.x * MT;              // 0 or 128
    const int n0 = blockIdx.y * NT;

    float acc[2][6][4];
    #pragma unroll
    for (int a=0;a<2;a++)
      #pragma unroll
      for (int b=0;b<6;b++)
        #pragma unroll
        for (int c=0;c<4;c++) acc[a][b][c] = 0.0f;
    float bsq6[6] = {0.f,0.f,0.f,0.f,0.f,0.f};  // row = i*16 + (tid>>4)

    const uint32_t smem_base = smem_u32(smem);
    const int br = tid >> 4;            // B base row (i adds 16)
    const int bq = tid & 15;            // quad column (4 floats)
    const float* Wbase = W + (size_t)n0*EMBED;
    const __nv_bfloat16* Abase = g_ebf + (size_t)m0*EMBED;

    float4 sB[6];                        // LDG staging for one chunk

    auto issueA = [&](int kc){
        uint32_t a_dst = smem_base + AOFF + (kc & 3)*A_ST;
        const __nv_bfloat16* a_src = Abase + kc*KC;
        #pragma unroll
        for (int p=0;p<4;p++){                 // A: 128 rows x 128B, swizzled
            int idx = p*THREADS + tid;
            int r = idx >> 3, q = idx & 7;
            uint32_t o = (uint32_t)(r*128 + q*16);
            const void* s = a_src + (size_t)r*EMBED + q*8;
            asm volatile("cp.async.cg.shared.global [%0], [%1], 16;\n"
                         :: "r"(a_dst + SW(o)), "l"(s));
        }
        asm volatile("cp.async.commit_group;\n");
    };

    auto ldgB = [&](int kc){
        const float* src = Wbase + kc*KC;
        #pragma unroll
        for (int i=0;i<6;i++)
            sB[i] = *reinterpret_cast<const float4*>(src + (size_t)(br + i*16)*EMBED + bq*4);
    };

    // cvt staged regs -> swizzled bf16 tile; accumulate ||w||^2 partials
    auto cvtStoreB = [&](int kc){
        char* Bb = smem + BBOFF + (kc & 1)*BB_ST;
        #pragma unroll
        for (int i=0;i<6;i++){
            float4 v = sB[i];
            bsq6[i] += fmaf(v.x,v.x, fmaf(v.y,v.y, fmaf(v.z,v.z, v.w*v.w)));
            uint32_t lo, hi;
            asm volatile("cvt.rn.bf16x2.f32 %0, %1, %2;\n" : "=r"(lo) : "f"(v.y), "f"(v.x));
            asm volatile("cvt.rn.bf16x2.f32 %0, %1, %2;\n" : "=r"(hi) : "f"(v.w), "f"(v.z));
            uint32_t o = (uint32_t)((br + i*16)*128 + bq*8);
            *reinterpret_cast<uint2*>(Bb + SW(o)) = make_uint2(lo, hi);
        }
    };

    auto mmachunk = [&](int kc){
        const char* Ab = smem + AOFF + (kc & 3)*A_ST;
        const char* Bb = smem + BBOFF + (kc & 1)*BB_ST;
        #pragma unroll
        for (int kk=0; kk<4; kk++){
            uint32_t af[2][4];
            #pragma unroll
            for (int mt=0; mt<2; mt++){
                int r = wm*32 + mt*16 + (lane & 15);
                uint32_t o = (uint32_t)(r*128 + kk*32 + (lane >> 4)*16);
                uint32_t addr = smem_u32(Ab) + SW(o);
                asm volatile("ldmatrix.sync.aligned.m8n8.x4.shared.b16 {%0,%1,%2,%3}, [%4];\n"
                             : "=r"(af[mt][0]), "=r"(af[mt][1]), "=r"(af[mt][2]), "=r"(af[mt][3])
                             : "r"(addr));
            }
            uint32_t bfr[6][2];
            #pragma unroll
            for (int pr=0; pr<3; pr++){              // nt pair {2pr, 2pr+1}
                int grp = lane >> 3;
                int row = wn*48 + pr*16 + ((grp >> 1) << 3) + (lane & 7);
                uint32_t o = (uint32_t)(row*128 + kk*32 + (grp & 1)*16);
                uint32_t addr = smem_u32(Bb) + SW(o);
                asm volatile("ldmatrix.sync.aligned.m8n8.x4.shared.b16 {%0,%1,%2,%3}, [%4];\n"
                             : "=r"(bfr[2*pr][0]), "=r"(bfr[2*pr][1]),
                               "=r"(bfr[2*pr+1][0]), "=r"(bfr[2*pr+1][1])
                             : "r"(addr));
            }
            #pragma unroll
            for (int mt=0; mt<2; mt++)
                #pragma unroll
                for (int nt=0; nt<6; nt++){
                    float* d = acc[mt][nt];
                    asm volatile(
                      "mma.sync.aligned.m16n8k16.row.col.f32.bf16.bf16.f32 "
                      "{%0,%1,%2,%3}, {%4,%5,%6,%7}, {%8,%9}, {%0,%1,%2,%3};\n"
                      : "+f"(d[0]), "+f"(d[1]), "+f"(d[2]), "+f"(d[3])
                      : "r"(af[mt][0]), "r"(af[mt][1]), "r"(af[mt][2]), "r"(af[mt][3]),
                        "r"(bfr[nt][0]), "r"(bfr[nt][1]));
                }
        }
    };

    // prologue: A chunks 0,1 in flight; B chunk 0 converted
    issueA(0);
    issueA(1);
    ldgB(0);
    cvtStoreB(0);

    #pragma unroll 1
    for (int kc=0; kc<CHUNKS; kc++){
        if (kc + 2 < CHUNKS) issueA(kc+2);
        if (kc + 1 < CHUNKS) ldgB(kc+1);
        if (kc + 2 < CHUNKS)      asm volatile("cp.async.wait_group 2;\n");
        else if (kc + 1 < CHUNKS) asm volatile("cp.async.wait_group 1;\n");
        else                      asm volatile("cp.async.wait_group 0;\n");
        __syncthreads();      // A(kc) + bb(kc) visible; prior-chunk reads done
        mmachunk(kc);
        if (kc + 1 < CHUNKS) cvtStoreB(kc+1);
    }

    // ||w||^2: reduce over the 16 lanes sharing a row, write s_wsq
    #pragma unroll
    for (int i=0;i<6;i++){
        float v = bsq6[i];
        v += __shfl_xor_sync(0xffffffffu, v, 1, 16);
        v += __shfl_xor_sync(0xffffffffu, v, 2, 16);
        v += __shfl_xor_sync(0xffffffffu, v, 4, 16);
        v += __shfl_xor_sync(0xffffffffu, v, 8, 16);
        if ((lane & 15) == 0) s_wsq[i*16 + (tid>>4)] = v;
    }
    __syncthreads();
    if (tid < NT) s_wsq[tid] = rsqrtf(fmaxf(s_wsq[tid], 1e-24f));
    __syncthreads();   // all MMA/smem reads done; safe to reuse pipe smem as epi

    // scale by 1/||w|| and stage warp tile (32 rows x 48 cols) in smem
    float* my_epi = epi + (size_t)warp * (32 * EPI_STRIDE);
    #pragma unroll
    for (int mt=0; mt<2; mt++)
        #pragma unroll
        for (int nt=0; nt<6; nt++){
            int c0 = wn*48 + nt*8 + 2*tg;
            float i0 = s_wsq[c0], i1 = s_wsq[c0+1];
            int r0 = mt*16 + g;
            int cc = nt*8 + 2*tg;
            my_epi[ r0     *EPI_STRIDE + cc    ] = acc[mt][nt][0]*i0;
            my_epi[ r0     *EPI_STRIDE + cc + 1] = acc[mt][nt][1]*i1;
            my_epi[(r0 + 8)*EPI_STRIDE + cc    ] = acc[mt][nt][2]*i0;
            my_epi[(r0 + 8)*EPI_STRIDE + cc + 1] = acc[mt][nt][3]*i1;
        }
    __syncwarp();

    // each lane owns one row of the 32x48 warp tile: max3 + sumexp
    {
        float partial = 0.0f;
        #pragma unroll
        for (int c=0; c<16; c++){
            float v0 = my_epi[lane*EPI_STRIDE + c*3    ];
            float v1 = my_epi[lane*EPI_STRIDE + c*3 + 1];
            float v2 = my_epi[lane*EPI_STRIDE + c*3 + 2];
            float cs = fmaxf(v0, fmaxf(v1, v2));
            partial += fexp(SCALE * cs);
        }
        atomicAdd(&g_sumexp[m0 + wm*32 + lane], partial);
    }

    // ── inline finalize by the last CTA (atomic ticket) ──
    __threadfence();
    __syncthreads();
    __shared__ unsigned int s_flag;
    if (tid == 0){
        unsigned int old = atomicAdd(&g_ticket, 1u);
        s_flag = (old == (unsigned)(TOTAL_CTAS - 1)) ? 1u : 0u;
    }
    __syncthreads();
    if (s_flag){
        __threadfence();
        float v = 0.0f;
        {
            float S = __ldcg(&g_sumexp[tid]) + g_expadj[tid];
            v = logf(S) - g_lablogit[tid];
        }
        #pragma unroll
        for (int o=16;o;o>>=1) v += __shfl_xor_sync(0xffffffffu, v, o);
        float* ws = epi;
        if ((tid & 31) == 0) ws[tid>>5] = v;
        __syncthreads();
        if (tid == 0){
            float s = 0.0f;
            #pragma unroll
            for (int i=0;i<8;i++) s += ws[i];
            out[0] = s * (1.0f/256.0f);
            g_ticket = 0;
        }
    }
}

extern "C" void kernel_launch(void* const* d_in, const int* in_sizes, int n_in,
                              void* d_out, int out_size){
    int ie = 0, il = 1, iw = 2;
    for (int i = 0; i < n_in; i++){
        if (in_sizes[i] == BATCH) il = i;
        else if (in_sizes[i] == BATCH*EMBED) ie = i;
        else if (in_sizes[i] == NSROWS*EMBED) iw = i;
    }
    const float* emb    = (const float*)d_in[ie];
    const void*  labels = (const void*)d_in[il];
    const float* W      = (const float*)d_in[iw];

    cudaFuncSetAttribute(arc_main, cudaFuncAttributeMaxDynamicSharedMemorySize, SMEM_BYTES);

    prep_label<<<320, 128>>>(emb, W, labels);
    dim3 grid(2, NCLS/32);   // x fastest: M-half pairs launch-adjacent
    arc_main<<<grid, THREADS, SMEM_BYTES>>>(W, (float*)d_out);
}